// round 7
// baseline (speedup 1.0000x reference)
#include <cuda_runtime.h>

// FwFM forward on GB300 — R6: row-pair packed accumulators over scalar x.
//  * 16 lanes/sample (lane owns dim d), 2 samples/warp, 128-thr blocks, grid 1024.
//  * x[39] scalar regs; tt[k] = packed f32x2 accumulator for rows (2k,2k+1).
//  * Column-major triangle: per column j, splat (x_j,x_j) once, then
//    tt[k] += (w_{2k,j}, w_{2k+1,j}) * xs  via LDG.128 -> 2x FFMA2.
//  * Pair weights pre-packed into a __device__ global by a tiny prep kernel
//    (runs once per launch; both launches are graph-capturable).
//  * Adjacent pairs (2k,2k+1) are 19 scalar FMAs; final combine is packed.

#define FIELDS 39
#define EDIM 16
#define BATCH 8192
#define SAMPLES_PER_BLOCK 8
#define THREADS 128
#define NQUADS 190            // sum over j of ceil(floor(j/2)/2)

typedef unsigned long long ull;

__device__ __align__(16) float g_pwq[NQUADS * 4]; // packed quads: rows 4m..4m+3 at column j
__device__ float g_wdiag[20];                     // w for pairs (2k,2k+1), k=0..18

__device__ __forceinline__ ull pk_zero() {
    ull v; asm("mov.b64 %0, {%1, %1};" : "=l"(v) : "f"(0.0f)); return v;
}
__device__ __forceinline__ ull pk_splat(float w) {
    ull v; asm("mov.b64 %0, {%1, %1};" : "=l"(v) : "f"(w)); return v;
}
__device__ __forceinline__ ull pk_pair(float a, float b) {
    ull v; asm("mov.b64 %0, {%1, %2};" : "=l"(v) : "f"(a), "f"(b)); return v;
}
__device__ __forceinline__ ull pk_fma(ull a, ull b, ull c) {
    ull r; asm("fma.rn.f32x2 %0, %1, %2, %3;" : "=l"(r) : "l"(a), "l"(b), "l"(c)); return r;
}
__device__ __forceinline__ ull pk_add(ull a, ull b) {
    ull r; asm("add.rn.f32x2 %0, %1, %2;" : "=l"(r) : "l"(a), "l"(b)); return r;
}
__device__ __forceinline__ void ldg2u64(const float* p, ull& a, ull& b) {
    asm("ld.global.nc.v2.u64 {%0, %1}, [%2];" : "=l"(a), "=l"(b) : "l"(p));
}

// ---- prep: pack pair weights (runs as 1 block, once per launch) ----
__global__ void fwfm_prep(const float* __restrict__ fw)
{
    const int t = threadIdx.x;
    if (t < NQUADS) {
        // locate column j and quad m for flat quad index t
        int qb = 0, j = 2, m = 0;
        for (int jj = 2; jj < FIELDS; jj++) {
            const int qn = ((jj >> 1) + 1) >> 1;
            if (t < qb + qn) { j = jj; m = t - qb; break; }
            qb += qn;
        }
        for (int r = 0; r < 4; r++) {
            const int i = 4 * m + r;               // row
            float v = 0.0f;
            if ((i | 1) < j) {                      // packed-pair validity
                const int off = 38 * i - (i * (i - 1)) / 2 + (j - i - 1);
                v = fw[off];
            }
            g_pwq[t * 4 + r] = v;
        }
    } else if (t < NQUADS + 19) {
        const int k = t - NQUADS;
        const int i = 2 * k;
        g_wdiag[k] = fw[38 * i - (i * (i - 1)) / 2];   // pair (2k, 2k+1)
    }
}

// ---- main kernel ----
__global__ __launch_bounds__(THREADS, 5)   // allow up to 102 regs
void fwfm_kernel(const int* __restrict__ inputs,
                 const float* __restrict__ emb,
                 const float* __restrict__ lw,
                 const float* __restrict__ bias,
                 float* __restrict__ out)
{
    __shared__ int idx_sh[SAMPLES_PER_BLOCK * FIELDS];

    const int tid = threadIdx.x;
    const int base = blockIdx.x * SAMPLES_PER_BLOCK * FIELDS;
    for (int k = tid; k < SAMPLES_PER_BLOCK * FIELDS; k += THREADS)
        idx_sh[k] = inputs[base + k];
    __syncthreads();

    const int warp = tid >> 5;
    const int lane = tid & 31;
    const int sub  = lane >> 4;       // sample within warp (0..1)
    const int d    = lane & 15;       // dim owned by this lane
    const int s_local = warp * 2 + sub;
    const int sample  = blockIdx.x * SAMPLES_PER_BLOCK + s_local;
    const int* my_idx = &idx_sh[s_local * FIELDS];

    // Gather: lane d loads dim d of each field (16 lanes cover the 64B row).
    float x[FIELDS];
#pragma unroll
    for (int f = 0; f < FIELDS; f++) {
        const int g = my_idx[f];
        x[f] = __ldg(emb + (size_t)g * EDIM + d);
    }

    // First-order partial: lane d covers fields d, d+16, d+32 (if present).
    float lin = lw[my_idx[d]] + lw[my_idx[d + 16]];
    if (d < FIELDS - 32) lin += lw[my_idx[d + 32]];

    // Second order, row-pair packed accumulators.
    ull tt[20];
#pragma unroll
    for (int k = 0; k < 20; k++) tt[k] = pk_zero();

    {
        int q = 0;                     // compile-time after full unroll
#pragma unroll
        for (int j = 2; j < FIELDS; j++) {
            const int nq = ((j >> 1) + 1) >> 1;
            const ull xs = pk_splat(x[j]);
#pragma unroll
            for (int m = 0; m < nq; m++) {
                ull wa, wb;
                ldg2u64(&g_pwq[(q + m) * 4], wa, wb);   // rows 4m..4m+3, col j
                tt[2 * m]     = pk_fma(wa, xs, tt[2 * m]);
                tt[2 * m + 1] = pk_fma(wb, xs, tt[2 * m + 1]);
            }
            q += nq;
        }
    }

    // Adjacent pairs (2k, 2k+1): scalar fixups.
    float acc_s = 0.0f;
#pragma unroll
    for (int k = 0; k < 19; k++)
        acc_s = fmaf(__ldg(&g_wdiag[k]) * x[2 * k], x[2 * k + 1], acc_s);

    // Combine: acc2 = sum_k pk(x_{2k}, x_{2k+1}) * tt[k]   (two chains)
    ull a0 = pk_zero(), a1 = pk_zero();
#pragma unroll
    for (int k = 0; k < 19; k += 2) {
        a0 = pk_fma(pk_pair(x[2 * k], x[2 * k + 1]), tt[k], a0);
        if (k + 1 < 19)
            a1 = pk_fma(pk_pair(x[2 * k + 2], x[2 * k + 3]), tt[k + 1], a1);
    }
    const ull a = pk_add(a0, a1);

    float lo, hi;
    asm("mov.b64 {%0, %1}, %2;" : "=f"(lo), "=f"(hi) : "l"(a));
    float v = lo + hi + acc_s + lin;

    // Reduce across the 16 lanes of this sample.
    v += __shfl_xor_sync(0xffffffffu, v, 8);
    v += __shfl_xor_sync(0xffffffffu, v, 4);
    v += __shfl_xor_sync(0xffffffffu, v, 2);
    v += __shfl_xor_sync(0xffffffffu, v, 1);

    if (d == 0)
        out[sample] = v + bias[0];
}

extern "C" void kernel_launch(void* const* d_in, const int* in_sizes, int n_in,
                              void* d_out, int out_size)
{
    const int*   inputs = (const int*)d_in[0];
    const float* emb    = (const float*)d_in[1];
    const float* fw     = (const float*)d_in[2];
    const float* lw     = (const float*)d_in[3];
    const float* bias   = (const float*)d_in[4];
    float*       out    = (float*)d_out;

    fwfm_prep<<<1, 256>>>(fw);
    fwfm_kernel<<<BATCH / SAMPLES_PER_BLOCK, THREADS>>>(inputs, emb, lw, bias, out);
}

// round 10
// speedup vs baseline: 1.6430x; 1.6430x over previous
#include <cuda_runtime.h>

// FwFM forward on GB300 — R8: row-pair packed strips over scalar x.
//  * 16 lanes/sample (lane owns dim d, scalar x[39] regs), 2 samples/warp,
//    128-thr blocks (8 samples), grid 1024.
//  * Pair triangle split into 5 strips of 8 rows. Per strip: 4 packed f32x2
//    accumulators (row pairs). Column sweep: splat {x_j,x_j} once, load 8
//    pre-paired weights {w_i,w_i+1} via two 16B broadcast LDS, 4 FFMA2.
//  * Weights zero-padded for invalid cells; staged to smem per block.
//  * Keeps R5 occupancy (~28 warps/SM) with R2-level instruction count.

#define FIELDS 39
#define EDIM 16
#define BATCH 8192
#define SAMPLES_PER_BLOCK 8
#define THREADS 128
#define WTOT 880             // sum over strips of (38-8s)*8

typedef unsigned long long ull;

__device__ __forceinline__ ull pk_zero() {
    ull v; asm("mov.b64 %0, {%1, %1};" : "=l"(v) : "f"(0.0f)); return v;
}
__device__ __forceinline__ ull pk_splat(float w) {
    ull v; asm("mov.b64 %0, {%1, %1};" : "=l"(v) : "f"(w)); return v;
}
__device__ __forceinline__ ull pk_pair(float a, float b) {
    ull v; asm("mov.b64 %0, {%1, %2};" : "=l"(v) : "f"(a), "f"(b)); return v;
}
__device__ __forceinline__ ull pk_fma(ull a, ull b, ull c) {
    ull r; asm("fma.rn.f32x2 %0, %1, %2, %3;" : "=l"(r) : "l"(a), "l"(b), "l"(c)); return r;
}
__device__ __forceinline__ ull pk_add(ull a, ull b) {
    ull r; asm("add.rn.f32x2 %0, %1, %2;" : "=l"(r) : "l"(a), "l"(b)); return r;
}

// Strip S covers rows [8S, 8S+8) and columns j = 8S+1 .. 38.
// Weight block base (in floats): 8*(38S - 4S(S-1)).
template<int S>
__device__ __forceinline__ void strip_acc(const float* __restrict__ x,
                                          const float* __restrict__ wsm,
                                          ull& a0, ull& a1)
{
    constexpr int R    = 8 * S;
    constexpr int NCOL = 38 - R;
    constexpr int BASE = 8 * (38 * S - 4 * S * (S - 1));

    ull t01 = pk_zero(), t23 = pk_zero(), t45 = pk_zero(), t67 = pk_zero();
#pragma unroll
    for (int c = 0; c < NCOL; c++) {
        const int j = R + 1 + c;
        const ulonglong2 wA = *reinterpret_cast<const ulonglong2*>(wsm + BASE + 8 * c);
        const ulonglong2 wB = *reinterpret_cast<const ulonglong2*>(wsm + BASE + 8 * c + 4);
        const ull xs = pk_splat(x[j]);
        t01 = pk_fma(wA.x, xs, t01);
        t23 = pk_fma(wA.y, xs, t23);
        t45 = pk_fma(wB.x, xs, t45);
        t67 = pk_fma(wB.y, xs, t67);
    }
    a0 = pk_fma(pk_pair(x[R + 0], x[R + 1]), t01, a0);
    a1 = pk_fma(pk_pair(x[R + 2], x[R + 3]), t23, a1);
    a0 = pk_fma(pk_pair(x[R + 4], x[R + 5]), t45, a0);
    a1 = pk_fma(pk_pair(x[R + 6], x[R + 7]), t67, a1);   // S=4 uses x[38], x[39]=0
}

__global__ __launch_bounds__(THREADS, 7)   // cap 73 regs -> 28 warps/SM
void fwfm_kernel(const int* __restrict__ inputs,
                 const float* __restrict__ emb,
                 const float* __restrict__ fw,
                 const float* __restrict__ lw,
                 const float* __restrict__ bias,
                 float* __restrict__ out)
{
    __shared__ __align__(16) float wsm[WTOT];
    __shared__ int idx_sh[SAMPLES_PER_BLOCK * FIELDS];

    const int tid = threadIdx.x;

    // Stage strip-blocked, zero-padded pair weights.
    for (int e = tid; e < WTOT; e += THREADS) {
        const int s = (e >= 832) ? 4 : (e >= 720) ? 3 : (e >= 544) ? 2
                    : (e >= 304) ? 1 : 0;
        const int basef = 8 * (38 * s - 4 * s * (s - 1));
        const int rel = e - basef;
        const int c = rel >> 3;          // column index within strip
        const int r = rel & 7;           // row within strip
        const int i = 8 * s + r;
        const int j = 8 * s + 1 + c;
        float w = 0.0f;
        if (i < j)                        // valid upper-triangle cell
            w = fw[38 * i - (i * (i - 1)) / 2 + (j - i - 1)];
        wsm[e] = w;
    }
    // Stage this block's indices (coalesced).
    const int base = blockIdx.x * SAMPLES_PER_BLOCK * FIELDS;
    for (int k = tid; k < SAMPLES_PER_BLOCK * FIELDS; k += THREADS)
        idx_sh[k] = inputs[base + k];
    __syncthreads();

    const int warp = tid >> 5;
    const int lane = tid & 31;
    const int sub  = lane >> 4;       // sample within warp (0..1)
    const int d    = lane & 15;       // dim owned by this lane
    const int s_local = warp * 2 + sub;
    const int sample  = blockIdx.x * SAMPLES_PER_BLOCK + s_local;
    const int* my_idx = &idx_sh[s_local * FIELDS];

    // Gather: lane d loads dim d of each field (16 lanes cover the 64B row).
    float x[FIELDS + 1];
#pragma unroll
    for (int f = 0; f < FIELDS; f++) {
        const int g = my_idx[f];
        x[f] = __ldg(emb + (size_t)g * EDIM + d);
    }
    x[FIELDS] = 0.0f;                 // pad row 39

    // First-order partial: lane d covers fields d, d+16, d+32 (if present).
    float lin = lw[my_idx[d]] + lw[my_idx[d + 16]];
    if (d < FIELDS - 32) lin += lw[my_idx[d + 32]];

    // Second order: 5 row strips, row-pair packed.
    ull a0 = pk_zero(), a1 = pk_zero();
    strip_acc<0>(x, wsm, a0, a1);
    strip_acc<1>(x, wsm, a0, a1);
    strip_acc<2>(x, wsm, a0, a1);
    strip_acc<3>(x, wsm, a0, a1);
    strip_acc<4>(x, wsm, a0, a1);
    const ull a = pk_add(a0, a1);

    float lo, hi;
    asm("mov.b64 {%0, %1}, %2;" : "=f"(lo), "=f"(hi) : "l"(a));
    float v = lo + hi + lin;

    // Reduce across the 16 lanes of this sample.
    v += __shfl_xor_sync(0xffffffffu, v, 8);
    v += __shfl_xor_sync(0xffffffffu, v, 4);
    v += __shfl_xor_sync(0xffffffffu, v, 2);
    v += __shfl_xor_sync(0xffffffffu, v, 1);

    if (d == 0)
        out[sample] = v + bias[0];
}

extern "C" void kernel_launch(void* const* d_in, const int* in_sizes, int n_in,
                              void* d_out, int out_size)
{
    const int*   inputs = (const int*)d_in[0];
    const float* emb    = (const float*)d_in[1];
    const float* fw     = (const float*)d_in[2];
    const float* lw     = (const float*)d_in[3];
    const float* bias   = (const float*)d_in[4];
    float*       out    = (float*)d_out;

    fwfm_kernel<<<BATCH / SAMPLES_PER_BLOCK, THREADS>>>(inputs, emb, fw, lw, bias, out);
}